// round 6
// baseline (speedup 1.0000x reference)
#include <cuda_runtime.h>
#include <cuda_bf16.h>
#include <cstdint>

// Problem constants (fixed by the dataset)
#define H    256
#define NMAX 8192
#define EMAX 8192
#define KTOT 512            // concatenated K dim: [xi | xj]

// ---------------- scratch (static __device__ — no allocations) ----------------
__device__ uint32_t      g_bits[(size_t)NMAX * (NMAX / 32)];  // 8 MB packed adjacency
__device__ __nv_bfloat16 g_Xhi[(size_t)NMAX * H];             // 4 MB bf16 hi of x
__device__ __nv_bfloat16 g_Xlo[(size_t)NMAX * H];             // 4 MB bf16 lo of x
__device__ __nv_bfloat16 g_Wthi[(size_t)H * KTOT];            // 256 KB: Wt[n][k] hi
__device__ __nv_bfloat16 g_Wtlo[(size_t)H * KTOT];            // 256 KB
__device__ float         g_t0[EMAX];                          // per-edge relu-dot, cols 0-127
__device__ float         g_t1[EMAX];                          // per-edge relu-dot, cols 128-255
__device__ float         g_s2[NMAX];                          // s2[n] = x2[n]·vcn
__device__ float         g_vcn[H];
__device__ float         g_vf[H];
__device__ float         g_ws2[H];
__device__ float         g_consts[4];                         // [0]=bcn·ws, [1]=bf·ws+bs, [2]=blin·vcn
__device__ unsigned char g_flag[NMAX];                        // adj row referenced by any edge?

// ---------------- helpers ----------------
__device__ __forceinline__ float warp_red(float v) {
#pragma unroll
    for (int o = 16; o; o >>= 1) v += __shfl_xor_sync(0xffffffffu, v, o);
    return v;
}

__device__ __forceinline__ float warp_dot256(const float* __restrict__ row,
                                             const float* __restrict__ vec, int lane) {
    float s = 0.f;
#pragma unroll
    for (int c = 0; c < H; c += 32) s = fmaf(row[c + lane], vec[c + lane], s);
    return warp_red(s);
}

// block-wide sum of one float per thread (256 threads); result valid in thread 0
__device__ __forceinline__ float block_red256(float v, float* sm8) {
    int lane = threadIdx.x & 31, w = threadIdx.x >> 5;
    v = warp_red(v);
    if (!lane) sm8[w] = v;
    __syncthreads();
    float t = 0.f;
    if (w == 0) {
        t = (lane < 8) ? sm8[lane] : 0.f;
        t += __shfl_xor_sync(0xffffffffu, t, 1);
        t += __shfl_xor_sync(0xffffffffu, t, 2);
        t += __shfl_xor_sync(0xffffffffu, t, 4);
    }
    return t;
}

__device__ __forceinline__ void mma16816(float c[4], const uint32_t a[4],
                                         uint32_t b0, uint32_t b1) {
    asm volatile(
        "mma.sync.aligned.m16n8k16.row.col.f32.bf16.bf16.f32 "
        "{%0,%1,%2,%3}, {%4,%5,%6,%7}, {%8,%9}, {%0,%1,%2,%3};"
        : "+f"(c[0]), "+f"(c[1]), "+f"(c[2]), "+f"(c[3])
        : "r"(a[0]), "r"(a[1]), "r"(a[2]), "r"(a[3]), "r"(b0), "r"(b1));
}

__device__ __forceinline__ void ldsm4(uint32_t r[4], uint32_t addr) {
    asm volatile("ldmatrix.sync.aligned.m8n8.x4.shared.b16 {%0,%1,%2,%3}, [%4];"
        : "=r"(r[0]), "=r"(r[1]), "=r"(r[2]), "=r"(r[3]) : "r"(addr));
}

// ---------------- combo head kernel: prep-x ∥ prep-W ∥ flag-zero ∥ k0a ----------------
__global__ void __launch_bounds__(256) combo_kernel(const float* __restrict__ x,
                                                    const float* __restrict__ Wi,
                                                    const float* __restrict__ Wj,
                                                    const float* __restrict__ Wcn,
                                                    const float* __restrict__ Wf,
                                                    const float* __restrict__ ws) {
    __shared__ float sm8[8];
    int bid = blockIdx.x;
    int tid = threadIdx.x;
    const int XB = (NMAX * H) / 1024;          // 2048 blocks: x split
    if (bid < XB) {
        int gid = bid * 256 + tid;
        float4 v = ((const float4*)x)[gid];
        __nv_bfloat16 hx = __float2bfloat16(v.x), hy = __float2bfloat16(v.y);
        __nv_bfloat16 hz = __float2bfloat16(v.z), hw = __float2bfloat16(v.w);
        __nv_bfloat16 lx = __float2bfloat16(v.x - __bfloat162float(hx));
        __nv_bfloat16 ly = __float2bfloat16(v.y - __bfloat162float(hy));
        __nv_bfloat16 lz = __float2bfloat16(v.z - __bfloat162float(hz));
        __nv_bfloat16 lw = __float2bfloat16(v.w - __bfloat162float(hw));
        ((__nv_bfloat162*)g_Xhi)[gid * 2 + 0] = __nv_bfloat162(hx, hy);
        ((__nv_bfloat162*)g_Xhi)[gid * 2 + 1] = __nv_bfloat162(hz, hw);
        ((__nv_bfloat162*)g_Xlo)[gid * 2 + 0] = __nv_bfloat162(lx, ly);
        ((__nv_bfloat162*)g_Xlo)[gid * 2 + 1] = __nv_bfloat162(lz, lw);
    } else if (bid < XB + H) {                 // 256 blocks: W transpose+split
        int n = bid - XB;
        for (int k = tid; k < KTOT; k += 256) {
            float w = (k < H) ? Wi[(size_t)k * H + n] : Wj[(size_t)(k - H) * H + n];
            __nv_bfloat16 hi = __float2bfloat16(w);
            __nv_bfloat16 lo = __float2bfloat16(w - __bfloat162float(hi));
            g_Wthi[(size_t)n * KTOT + k] = hi;
            g_Wtlo[(size_t)n * KTOT + k] = lo;
        }
    } else if (bid < XB + H + 32) {            // 32 blocks: flag zero
        g_flag[(bid - XB - H) * 256 + tid] = 0;
    } else {                                    // 512 blocks: k0a rows
        int r = bid - XB - H - 32;              // 0..511
        const float* W = (r < H) ? (Wcn + (size_t)r * H) : (Wf + (size_t)(r - H) * H);
        float d = block_red256(W[tid] * ws[tid], sm8);
        if (tid == 0) {
            if (r < H) g_vcn[r] = d;
            else       g_vf[r - H] = d;
        }
    }
}

// ---------------- flagset: mark adj rows referenced by edges ----------------
__global__ void __launch_bounds__(256) flagset_kernel(const int* __restrict__ tei, int twoE) {
    int gid = blockIdx.x * 256 + threadIdx.x;
    if (gid < twoE) g_flag[tei[gid]] = 1;
}

// ---------------- k0b (widened): ws2 = vcn + Wlin@vcn + scalar consts ----------------
__global__ void __launch_bounds__(256) k0b_kernel(const float* __restrict__ Wlin,
                                                  const float* __restrict__ blin,
                                                  const float* __restrict__ bcn,
                                                  const float* __restrict__ bf,
                                                  const float* __restrict__ ws,
                                                  const float* __restrict__ bs) {
    __shared__ float sm8[8];
    int b = blockIdx.x;
    int tid = threadIdx.x;
    if (b < H) {
        float d = block_red256(Wlin[(size_t)b * H + tid] * g_vcn[tid], sm8);
        if (tid == 0) g_ws2[b] = g_vcn[b] + d;
    } else if (b == H) {
        float d = block_red256(blin[tid] * g_vcn[tid], sm8);
        if (tid == 0) g_consts[2] = d;
    } else if (b == H + 1) {
        float d = block_red256(bcn[tid] * ws[tid], sm8);
        if (tid == 0) g_consts[0] = d;
    } else {
        float d = block_red256(bf[tid] * ws[tid], sm8);
        if (tid == 0) g_consts[1] = d + bs[0];
    }
}

// ---------------- pack: one warp packs 2048 adj floats, software-pipelined ----------------
// Rolling double-buffer of 4-float4 batches: the next batch's 16 lines are in
// flight while the current batch runs its nibble/shfl packing (duty-cycle fix).
__device__ __forceinline__ void pack_warp(const float* __restrict__ adj,
                                          size_t gw, int lane) {
    if (!g_flag[gw >> 2]) return;                 // adj row never referenced
    const float4* base = (const float4*)(adj + gw * 2048);
    int grp = lane >> 3;                          // 4 groups of 8 lanes
    int sh  = (lane & 7) * 4;
    float4 v[2][4];
#pragma unroll
    for (int i = 0; i < 4; i++) v[0][i] = __ldcs(base + (size_t)i * 32 + lane);
#pragma unroll
    for (int b = 0; b < 4; b++) {
        if (b < 3) {
#pragma unroll
            for (int i = 0; i < 4; i++)
                v[(b + 1) & 1][i] = __ldcs(base + (size_t)((b + 1) * 4 + i) * 32 + lane);
        }
#pragma unroll
        for (int i = 0; i < 4; i++) {
            float4 t = v[b & 1][i];
            uint32_t nib = (uint32_t)(t.x != 0.f)
                         | ((uint32_t)(t.y != 0.f) << 1)
                         | ((uint32_t)(t.z != 0.f) << 2)
                         | ((uint32_t)(t.w != 0.f) << 3);
            uint32_t w = nib << sh;
            w |= __shfl_xor_sync(0xffffffffu, w, 1);
            w |= __shfl_xor_sync(0xffffffffu, w, 2);
            w |= __shfl_xor_sync(0xffffffffu, w, 4);
            if ((lane & 7) == 0)
                g_bits[gw * 64 + (size_t)(b * 4 + i) * 4 + grp] = w;
        }
    }
}

// ---------------- tensor-core edge GEMM body: 64 edges x 128 cols, K=512 ----------------
// split-bf16 3-pass (hi*hi + hi*lo + lo*hi), ldmatrix fragments, acc[8][4]=32 regs.
#define ROWPAD 12
__device__ __forceinline__ void gemm_block(int h, const int* __restrict__ tei, int E,
                                           const float* __restrict__ bi,
                                           const float* __restrict__ bj,
                                           uint32_t* smem) {
    uint32_t* AsHi = smem;                   // 64*12
    uint32_t* AsLo = smem + 768;
    uint32_t* BsHi = smem + 1536;            // 128*12
    uint32_t* BsLo = smem + 3072;
    float*    tsum = (float*)(smem + 4608);  // [2][64]
    int*      eidx = (int*)(smem + 4736);    // [64 src][64 dst]

    int np = h & 1;                          // column half
    int eb = h >> 1;                         // edge tile
    int ebase = eb * 64;

    int tid = threadIdx.x;
    int lane = tid & 31, wid = tid >> 5;
    int wm = wid & 3, wn = wid >> 2;

    if (tid < 64) {
        eidx[tid]      = tei[ebase + tid];
        eidx[64 + tid] = tei[E + ebase + tid];
    }
    __syncthreads();

    int arow = tid >> 2, aq = tid & 3;
    int brow = tid >> 1, bh2 = tid & 1;

    uint32_t asHiB = (uint32_t)__cvta_generic_to_shared(AsHi);
    uint32_t asLoB = (uint32_t)__cvta_generic_to_shared(AsLo);
    uint32_t bsHiB = (uint32_t)__cvta_generic_to_shared(BsHi);
    uint32_t bsLoB = (uint32_t)__cvta_generic_to_shared(BsLo);
    uint32_t aoff = (uint32_t)((wm * 16 + (lane & 15)) * 48 + (lane >> 4) * 16);
    uint32_t boff[4];
#pragma unroll
    for (int jj = 0; jj < 4; jj++)
        boff[jj] = (uint32_t)((wn * 64 + jj * 16 + (lane & 15)) * 48 + (lane >> 4) * 16);

    float acc[8][4];
#pragma unroll
    for (int j = 0; j < 8; j++)
#pragma unroll
        for (int q = 0; q < 4; q++) acc[j][q] = 0.f;

    for (int ks = 0; ks < KTOT / 16; ks++) {
        int k0 = ks * 16;
        {
            int node = eidx[(k0 < H ? 0 : 64) + arow];
            int gc = (k0 & (H - 1)) + aq * 4;
            uint2 vh = *(const uint2*)(g_Xhi + (size_t)node * H + gc);
            uint2 vl = *(const uint2*)(g_Xlo + (size_t)node * H + gc);
            AsHi[arow * ROWPAD + aq * 2 + 0] = vh.x;
            AsHi[arow * ROWPAD + aq * 2 + 1] = vh.y;
            AsLo[arow * ROWPAD + aq * 2 + 0] = vl.x;
            AsLo[arow * ROWPAD + aq * 2 + 1] = vl.y;
        }
        {
            size_t goff = (size_t)(np * 128 + brow) * KTOT + k0 + bh2 * 8;
            *(uint4*)&BsHi[brow * ROWPAD + bh2 * 4] = *(const uint4*)(g_Wthi + goff);
            *(uint4*)&BsLo[brow * ROWPAD + bh2 * 4] = *(const uint4*)(g_Wtlo + goff);
        }
        __syncthreads();

        uint32_t ah[4], al[4];
        ldsm4(ah, asHiB + aoff);
        ldsm4(al, asLoB + aoff);
#pragma unroll
        for (int jj = 0; jj < 4; jj++) {
            uint32_t bhf[4], blf[4];
            ldsm4(bhf, bsHiB + boff[jj]);
            ldsm4(blf, bsLoB + boff[jj]);
            mma16816(acc[2 * jj],     ah, bhf[0], bhf[2]);
            mma16816(acc[2 * jj],     ah, blf[0], blf[2]);
            mma16816(acc[2 * jj],     al, bhf[0], bhf[2]);
            mma16816(acc[2 * jj + 1], ah, bhf[1], bhf[3]);
            mma16816(acc[2 * jj + 1], ah, blf[1], blf[3]);
            mma16816(acc[2 * jj + 1], al, bhf[1], bhf[3]);
        }
        __syncthreads();
    }

    float tp0 = 0.f, tp1 = 0.f;
#pragma unroll
    for (int j = 0; j < 8; j++) {
        int col = np * 128 + wn * 64 + j * 8 + (lane & 3) * 2;
        float b0 = bi[col] + bj[col];
        float b1 = bi[col + 1] + bj[col + 1];
        float v0 = g_vf[col], v1 = g_vf[col + 1];
        tp0 += fmaxf(acc[j][0] + b0, 0.f) * v0 + fmaxf(acc[j][1] + b1, 0.f) * v1;
        tp1 += fmaxf(acc[j][2] + b0, 0.f) * v0 + fmaxf(acc[j][3] + b1, 0.f) * v1;
    }
    tp0 += __shfl_xor_sync(0xffffffffu, tp0, 1);
    tp0 += __shfl_xor_sync(0xffffffffu, tp0, 2);
    tp1 += __shfl_xor_sync(0xffffffffu, tp1, 1);
    tp1 += __shfl_xor_sync(0xffffffffu, tp1, 2);
    if ((lane & 3) == 0) {
        int r = wm * 16 + (lane >> 2);
        tsum[wn * 64 + r] = tp0;
        tsum[wn * 64 + r + 8] = tp1;
    }
    __syncthreads();
    if (tid < 64) {
        float v = tsum[tid] + tsum[64 + tid];
        if (np == 0) g_t0[ebase + tid] = v;
        else         g_t1[ebase + tid] = v;
    }
}

// ---------------- fused kernel: pack ∪ tensor-GEMM ∪ s2 ----------------
__global__ void __launch_bounds__(256, 3) fused_kernel(const float* __restrict__ x,
                                                       const float* __restrict__ adj,
                                                       const int* __restrict__ tei,
                                                       const float* __restrict__ bi,
                                                       const float* __restrict__ bj,
                                                       int N, int E) {
    __shared__ uint32_t smem[4864];   // 19 KB (gemm role only)

    const int nbGemm = (E / 64) * 2;  // 256
    const int nbS2   = N / 8;         // 1024
    int bid = blockIdx.x;
    int warp = threadIdx.x >> 5;
    int lane = threadIdx.x & 31;

    if (bid < 2 * nbGemm) {
        int half = bid >> 1;
        if ((bid & 1) == 0) {
            gemm_block(half, tei, E, bi, bj, smem);
        } else {
            pack_warp(adj, (size_t)half * 8 + warp, lane);
        }
    } else if (bid < 2 * nbGemm + nbS2) {
        int node = (bid - 2 * nbGemm) * 8 + warp;
        if (node < N) {
            float d = warp_dot256(x + (size_t)node * H, g_ws2, lane);
            if (!lane) g_s2[node] = d + g_consts[2];
        }
    } else {
        int pb = nbGemm + (bid - 2 * nbGemm - nbS2);
        pack_warp(adj, (size_t)pb * 8 + warp, lane);
    }
}

// ---------------- final edge kernel ----------------
__global__ void __launch_bounds__(256) edge_kernel(const int* __restrict__ tei, int E, int nwords,
                                                   const float* __restrict__ beta_p,
                                                   const int* __restrict__ boolen_p,
                                                   float* __restrict__ out) {
    int gw = (blockIdx.x * blockDim.x + threadIdx.x) >> 5;
    int lane = threadIdx.x & 31;
    if (gw >= E) return;

    int src = tei[gw];
    int dst = tei[E + gw];

    const uint32_t* bsrc = g_bits + (size_t)src * nwords;
    const uint32_t* bdst = g_bits + (size_t)dst * nwords;

    float s = 0.f;
    int rounds = nwords >> 5;          // 8 for N=8192
    for (int rb = 0; rb < rounds; rb += 8) {
        uint32_t aw[8], bw[8];
#pragma unroll
        for (int i = 0; i < 8; i++) {
            int w = lane + ((rb + i) << 5);
            aw[i] = bsrc[w];
            bw[i] = bdst[w];
        }
#pragma unroll
        for (int i = 0; i < 8; i++) {
            int w = lane + ((rb + i) << 5);
            uint32_t a = aw[i] & bw[i];
            while (a) {
                int b = __ffs(a) - 1;
                a &= a - 1;
                s += g_s2[(w << 5) + b];
            }
        }
    }
    float S = warp_red(s);

    if (!lane) {
        float beta = beta_p[0];
        float u = g_t0[gw] + g_t1[gw] + beta * (S + g_consts[0]) + g_consts[1];
        bool pos = boolen_p ? (boolen_p[0] != 0) : true;
        float v = pos ? u : -u;
        out[gw] = fmaxf(-v, 0.f) + log1pf(expf(-fabsf(v)));  // softplus(-v)
    }
}

// ---------------- launch ----------------
extern "C" void kernel_launch(void* const* d_in, const int* in_sizes, int n_in,
                              void* d_out, int out_size) {
    const float* x    = (const float*)d_in[0];
    const float* adj  = (const float*)d_in[1];
    const int*   tei  = (const int*)d_in[2];
    const float* Wlin = (const float*)d_in[3];
    const float* blin = (const float*)d_in[4];
    const float* Wcn  = (const float*)d_in[5];
    const float* bcn  = (const float*)d_in[6];
    const float* Wi   = (const float*)d_in[7];
    const float* bi   = (const float*)d_in[8];
    const float* Wj   = (const float*)d_in[9];
    const float* bj   = (const float*)d_in[10];
    const float* Wf   = (const float*)d_in[11];
    const float* bf   = (const float*)d_in[12];
    const float* ws   = (const float*)d_in[13];
    const float* bs   = (const float*)d_in[14];
    const float* beta = (const float*)d_in[15];
    const int* boolen = (n_in > 16) ? (const int*)d_in[16] : nullptr;
    float* out = (float*)d_out;

    const int N = in_sizes[0] / H;   // 8192 nodes
    const int E = in_sizes[2] / 2;   // 8192 edges
    const int nwords = N / 32;       // 256 words per adjacency row

    // 1) combo head: x split ∥ W split ∥ flag zero ∥ k0a (independent work, one launch)
    combo_kernel<<<(NMAX * H) / 1024 + H + 32 + 2 * H, 256>>>(x, Wi, Wj, Wcn, Wf, ws);
    // 2) flags (after zeroing), then k0b (needs vcn)
    flagset_kernel<<<(2 * E + 255) / 256, 256>>>(tei, 2 * E);
    k0b_kernel<<<H + 3, 256>>>(Wlin, blin, bcn, bf, ws, bs);
    // 3) fused: pipelined pack (DRAM) + tensor GEMM + s2 GEMV
    {
        int nbGemm = (E / 64) * 2;                        // 256
        int nbS2   = N / 8;                               // 1024
        int nbPack = (int)((long long)N * N / 2048 / 8);  // 4096
        int total = nbGemm + nbS2 + nbPack;               // 5376
        fused_kernel<<<total, 256>>>(x, adj, tei, bi, bj, N, E);
    }
    // 4) per-edge: CN bit-AND gather + combine + softplus
    edge_kernel<<<(E + 7) / 8, 256>>>(tei, E, nwords, beta, boolen, out);
}

// round 7
// speedup vs baseline: 1.1159x; 1.1159x over previous
#include <cuda_runtime.h>
#include <cuda_bf16.h>
#include <cstdint>

// Problem constants (fixed by the dataset)
#define H    256
#define NMAX 8192
#define EMAX 8192
#define KTOT 512            // concatenated K dim: [xi | xj]

// ---------------- scratch (static __device__ — no allocations) ----------------
__device__ uint32_t      g_bits[(size_t)NMAX * (NMAX / 32)];  // 8 MB packed adjacency (lane-local layout)
__device__ __nv_bfloat16 g_Xhi[(size_t)NMAX * H];             // 4 MB bf16 hi of x
__device__ __nv_bfloat16 g_Xlo[(size_t)NMAX * H];             // 4 MB bf16 lo of x
__device__ __nv_bfloat16 g_Wthi[(size_t)H * KTOT];            // 256 KB: Wt[n][k] hi
__device__ __nv_bfloat16 g_Wtlo[(size_t)H * KTOT];            // 256 KB
__device__ float         g_t0[EMAX];                          // per-edge relu-dot, cols 0-127
__device__ float         g_t1[EMAX];                          // per-edge relu-dot, cols 128-255
__device__ float         g_s2[NMAX];                          // s2[n] = x2[n]·vcn
__device__ float         g_vcn[H];
__device__ float         g_vf[H];
__device__ float         g_ws2[H];
__device__ float         g_consts[4];                         // [0]=bcn·ws, [1]=bf·ws+bs, [2]=blin·vcn
__device__ unsigned char g_flag[NMAX];                        // adj row referenced by any edge?

// Bit layout (pack/decode contract):
//   chunk gw covers 2048 floats at adj + gw*2048 (4 chunks per adjacency row).
//   lane L, iter i (0..15) packs float4 at float-offset i*128 + L*4 into nibble i.
//   word = g_bits[gw*64 + L*2 + half], half = i>>3, bit b = (i&7)*4 + component j.
//   decode: node = gw*2048 + half*1024 + (b>>2)*128 + L*4 + (b&3).

// ---------------- helpers ----------------
__device__ __forceinline__ float warp_red(float v) {
#pragma unroll
    for (int o = 16; o; o >>= 1) v += __shfl_xor_sync(0xffffffffu, v, o);
    return v;
}

__device__ __forceinline__ float warp_dot256(const float* __restrict__ row,
                                             const float* __restrict__ vec, int lane) {
    float s = 0.f;
#pragma unroll
    for (int c = 0; c < H; c += 32) s = fmaf(row[c + lane], vec[c + lane], s);
    return warp_red(s);
}

// block-wide sum of one float per thread (256 threads); result valid in thread 0
__device__ __forceinline__ float block_red256(float v, float* sm8) {
    int lane = threadIdx.x & 31, w = threadIdx.x >> 5;
    v = warp_red(v);
    if (!lane) sm8[w] = v;
    __syncthreads();
    float t = 0.f;
    if (w == 0) {
        t = (lane < 8) ? sm8[lane] : 0.f;
        t += __shfl_xor_sync(0xffffffffu, t, 1);
        t += __shfl_xor_sync(0xffffffffu, t, 2);
        t += __shfl_xor_sync(0xffffffffu, t, 4);
    }
    return t;
}

__device__ __forceinline__ void mma16816(float c[4], const uint32_t a[4],
                                         uint32_t b0, uint32_t b1) {
    asm volatile(
        "mma.sync.aligned.m16n8k16.row.col.f32.bf16.bf16.f32 "
        "{%0,%1,%2,%3}, {%4,%5,%6,%7}, {%8,%9}, {%0,%1,%2,%3};"
        : "+f"(c[0]), "+f"(c[1]), "+f"(c[2]), "+f"(c[3])
        : "r"(a[0]), "r"(a[1]), "r"(a[2]), "r"(a[3]), "r"(b0), "r"(b1));
}

__device__ __forceinline__ void ldsm4(uint32_t r[4], uint32_t addr) {
    asm volatile("ldmatrix.sync.aligned.m8n8.x4.shared.b16 {%0,%1,%2,%3}, [%4];"
        : "=r"(r[0]), "=r"(r[1]), "=r"(r[2]), "=r"(r[3]) : "r"(addr));
}

// ---------------- combo head kernel: prep-x ∥ prep-W ∥ flag-zero ∥ k0a ----------------
__global__ void __launch_bounds__(256) combo_kernel(const float* __restrict__ x,
                                                    const float* __restrict__ Wi,
                                                    const float* __restrict__ Wj,
                                                    const float* __restrict__ Wcn,
                                                    const float* __restrict__ Wf,
                                                    const float* __restrict__ ws) {
    __shared__ float sm8[8];
    int bid = blockIdx.x;
    int tid = threadIdx.x;
    const int XB = (NMAX * H) / 1024;          // 2048 blocks: x split
    if (bid < XB) {
        int gid = bid * 256 + tid;
        float4 v = ((const float4*)x)[gid];
        __nv_bfloat16 hx = __float2bfloat16(v.x), hy = __float2bfloat16(v.y);
        __nv_bfloat16 hz = __float2bfloat16(v.z), hw = __float2bfloat16(v.w);
        __nv_bfloat16 lx = __float2bfloat16(v.x - __bfloat162float(hx));
        __nv_bfloat16 ly = __float2bfloat16(v.y - __bfloat162float(hy));
        __nv_bfloat16 lz = __float2bfloat16(v.z - __bfloat162float(hz));
        __nv_bfloat16 lw = __float2bfloat16(v.w - __bfloat162float(hw));
        ((__nv_bfloat162*)g_Xhi)[gid * 2 + 0] = __nv_bfloat162(hx, hy);
        ((__nv_bfloat162*)g_Xhi)[gid * 2 + 1] = __nv_bfloat162(hz, hw);
        ((__nv_bfloat162*)g_Xlo)[gid * 2 + 0] = __nv_bfloat162(lx, ly);
        ((__nv_bfloat162*)g_Xlo)[gid * 2 + 1] = __nv_bfloat162(lz, lw);
    } else if (bid < XB + H) {                 // 256 blocks: W transpose+split
        int n = bid - XB;
        for (int k = tid; k < KTOT; k += 256) {
            float w = (k < H) ? Wi[(size_t)k * H + n] : Wj[(size_t)(k - H) * H + n];
            __nv_bfloat16 hi = __float2bfloat16(w);
            __nv_bfloat16 lo = __float2bfloat16(w - __bfloat162float(hi));
            g_Wthi[(size_t)n * KTOT + k] = hi;
            g_Wtlo[(size_t)n * KTOT + k] = lo;
        }
    } else if (bid < XB + H + 32) {            // 32 blocks: flag zero
        g_flag[(bid - XB - H) * 256 + tid] = 0;
    } else {                                    // 512 blocks: k0a rows
        int r = bid - XB - H - 32;              // 0..511
        const float* W = (r < H) ? (Wcn + (size_t)r * H) : (Wf + (size_t)(r - H) * H);
        float d = block_red256(W[tid] * ws[tid], sm8);
        if (tid == 0) {
            if (r < H) g_vcn[r] = d;
            else       g_vf[r - H] = d;
        }
    }
}

// ---------------- flagset: mark adj rows referenced by edges ----------------
__global__ void __launch_bounds__(256) flagset_kernel(const int* __restrict__ tei, int twoE) {
    int gid = blockIdx.x * 256 + threadIdx.x;
    if (gid < twoE) g_flag[tei[gid]] = 1;
}

// ---------------- k0b: ws2 = vcn + Wlin@vcn + scalar consts ----------------
__global__ void __launch_bounds__(256) k0b_kernel(const float* __restrict__ Wlin,
                                                  const float* __restrict__ blin,
                                                  const float* __restrict__ bcn,
                                                  const float* __restrict__ bf,
                                                  const float* __restrict__ ws,
                                                  const float* __restrict__ bs) {
    __shared__ float sm8[8];
    int b = blockIdx.x;
    int tid = threadIdx.x;
    if (b < H) {
        float d = block_red256(Wlin[(size_t)b * H + tid] * g_vcn[tid], sm8);
        if (tid == 0) g_ws2[b] = g_vcn[b] + d;
    } else if (b == H) {
        float d = block_red256(blin[tid] * g_vcn[tid], sm8);
        if (tid == 0) g_consts[2] = d;
    } else if (b == H + 1) {
        float d = block_red256(bcn[tid] * ws[tid], sm8);
        if (tid == 0) g_consts[0] = d;
    } else {
        float d = block_red256(bf[tid] * ws[tid], sm8);
        if (tid == 0) g_consts[1] = d + bs[0];
    }
}

// ---------------- pack: lane-local, shfl-free ----------------
// 16 front-batched LDG.128 per lane (64 lines in flight per warp), pure-ALU
// nibble packing, single uint2 store. No ballots, no shuffles.
__device__ __forceinline__ void pack_warp(const float* __restrict__ adj,
                                          size_t gw, int lane) {
    if (!g_flag[gw >> 2]) return;                 // adj row never referenced
    const float4* base = (const float4*)(adj + gw * 2048);
    float4 v[16];
#pragma unroll
    for (int i = 0; i < 16; i++)
        v[i] = __ldcs(base + (size_t)i * 32 + lane);
    uint32_t w0 = 0, w1 = 0;
#pragma unroll
    for (int i = 0; i < 8; i++) {
        uint32_t nib = (uint32_t)(v[i].x != 0.f)
                     | ((uint32_t)(v[i].y != 0.f) << 1)
                     | ((uint32_t)(v[i].z != 0.f) << 2)
                     | ((uint32_t)(v[i].w != 0.f) << 3);
        w0 |= nib << (i * 4);
    }
#pragma unroll
    for (int i = 0; i < 8; i++) {
        uint32_t nib = (uint32_t)(v[8 + i].x != 0.f)
                     | ((uint32_t)(v[8 + i].y != 0.f) << 1)
                     | ((uint32_t)(v[8 + i].z != 0.f) << 2)
                     | ((uint32_t)(v[8 + i].w != 0.f) << 3);
        w1 |= nib << (i * 4);
    }
    ((uint2*)(g_bits + gw * 64))[lane] = make_uint2(w0, w1);
}

// ---------------- tensor-core edge GEMM body: 64 edges x 128 cols, K=512 ----------------
#define ROWPAD 12
__device__ __forceinline__ void gemm_block(int h, const int* __restrict__ tei, int E,
                                           const float* __restrict__ bi,
                                           const float* __restrict__ bj,
                                           uint32_t* smem) {
    uint32_t* AsHi = smem;                   // 64*12
    uint32_t* AsLo = smem + 768;
    uint32_t* BsHi = smem + 1536;            // 128*12
    uint32_t* BsLo = smem + 3072;
    float*    tsum = (float*)(smem + 4608);  // [2][64]
    int*      eidx = (int*)(smem + 4736);    // [64 src][64 dst]

    int np = h & 1;                          // column half
    int eb = h >> 1;                         // edge tile
    int ebase = eb * 64;

    int tid = threadIdx.x;
    int lane = tid & 31, wid = tid >> 5;
    int wm = wid & 3, wn = wid >> 2;

    if (tid < 64) {
        eidx[tid]      = tei[ebase + tid];
        eidx[64 + tid] = tei[E + ebase + tid];
    }
    __syncthreads();

    int arow = tid >> 2, aq = tid & 3;
    int brow = tid >> 1, bh2 = tid & 1;

    uint32_t asHiB = (uint32_t)__cvta_generic_to_shared(AsHi);
    uint32_t asLoB = (uint32_t)__cvta_generic_to_shared(AsLo);
    uint32_t bsHiB = (uint32_t)__cvta_generic_to_shared(BsHi);
    uint32_t bsLoB = (uint32_t)__cvta_generic_to_shared(BsLo);
    uint32_t aoff = (uint32_t)((wm * 16 + (lane & 15)) * 48 + (lane >> 4) * 16);
    uint32_t boff[4];
#pragma unroll
    for (int jj = 0; jj < 4; jj++)
        boff[jj] = (uint32_t)((wn * 64 + jj * 16 + (lane & 15)) * 48 + (lane >> 4) * 16);

    float acc[8][4];
#pragma unroll
    for (int j = 0; j < 8; j++)
#pragma unroll
        for (int q = 0; q < 4; q++) acc[j][q] = 0.f;

    for (int ks = 0; ks < KTOT / 16; ks++) {
        int k0 = ks * 16;
        {
            int node = eidx[(k0 < H ? 0 : 64) + arow];
            int gc = (k0 & (H - 1)) + aq * 4;
            uint2 vh = *(const uint2*)(g_Xhi + (size_t)node * H + gc);
            uint2 vl = *(const uint2*)(g_Xlo + (size_t)node * H + gc);
            AsHi[arow * ROWPAD + aq * 2 + 0] = vh.x;
            AsHi[arow * ROWPAD + aq * 2 + 1] = vh.y;
            AsLo[arow * ROWPAD + aq * 2 + 0] = vl.x;
            AsLo[arow * ROWPAD + aq * 2 + 1] = vl.y;
        }
        {
            size_t goff = (size_t)(np * 128 + brow) * KTOT + k0 + bh2 * 8;
            *(uint4*)&BsHi[brow * ROWPAD + bh2 * 4] = *(const uint4*)(g_Wthi + goff);
            *(uint4*)&BsLo[brow * ROWPAD + bh2 * 4] = *(const uint4*)(g_Wtlo + goff);
        }
        __syncthreads();

        uint32_t ah[4], al[4];
        ldsm4(ah, asHiB + aoff);
        ldsm4(al, asLoB + aoff);
#pragma unroll
        for (int jj = 0; jj < 4; jj++) {
            uint32_t bhf[4], blf[4];
            ldsm4(bhf, bsHiB + boff[jj]);
            ldsm4(blf, bsLoB + boff[jj]);
            mma16816(acc[2 * jj],     ah, bhf[0], bhf[2]);
            mma16816(acc[2 * jj],     ah, blf[0], blf[2]);
            mma16816(acc[2 * jj],     al, bhf[0], bhf[2]);
            mma16816(acc[2 * jj + 1], ah, bhf[1], bhf[3]);
            mma16816(acc[2 * jj + 1], ah, blf[1], blf[3]);
            mma16816(acc[2 * jj + 1], al, bhf[1], bhf[3]);
        }
        __syncthreads();
    }

    float tp0 = 0.f, tp1 = 0.f;
#pragma unroll
    for (int j = 0; j < 8; j++) {
        int col = np * 128 + wn * 64 + j * 8 + (lane & 3) * 2;
        float b0 = bi[col] + bj[col];
        float b1 = bi[col + 1] + bj[col + 1];
        float v0 = g_vf[col], v1 = g_vf[col + 1];
        tp0 += fmaxf(acc[j][0] + b0, 0.f) * v0 + fmaxf(acc[j][1] + b1, 0.f) * v1;
        tp1 += fmaxf(acc[j][2] + b0, 0.f) * v0 + fmaxf(acc[j][3] + b1, 0.f) * v1;
    }
    tp0 += __shfl_xor_sync(0xffffffffu, tp0, 1);
    tp0 += __shfl_xor_sync(0xffffffffu, tp0, 2);
    tp1 += __shfl_xor_sync(0xffffffffu, tp1, 1);
    tp1 += __shfl_xor_sync(0xffffffffu, tp1, 2);
    if ((lane & 3) == 0) {
        int r = wm * 16 + (lane >> 2);
        tsum[wn * 64 + r] = tp0;
        tsum[wn * 64 + r + 8] = tp1;
    }
    __syncthreads();
    if (tid < 64) {
        float v = tsum[tid] + tsum[64 + tid];
        if (np == 0) g_t0[ebase + tid] = v;
        else         g_t1[ebase + tid] = v;
    }
}

// ---------------- fused kernel: pack ∪ tensor-GEMM ∪ s2 ----------------
__global__ void __launch_bounds__(256, 3) fused_kernel(const float* __restrict__ x,
                                                       const float* __restrict__ adj,
                                                       const int* __restrict__ tei,
                                                       const float* __restrict__ bi,
                                                       const float* __restrict__ bj,
                                                       int N, int E) {
    __shared__ uint32_t smem[4864];   // 19 KB (gemm role only)

    const int nbGemm = (E / 64) * 2;  // 256
    const int nbS2   = N / 8;         // 1024
    int bid = blockIdx.x;
    int warp = threadIdx.x >> 5;
    int lane = threadIdx.x & 31;

    if (bid < 2 * nbGemm) {
        int half = bid >> 1;
        if ((bid & 1) == 0) {
            gemm_block(half, tei, E, bi, bj, smem);
        } else {
            pack_warp(adj, (size_t)half * 8 + warp, lane);
        }
    } else if (bid < 2 * nbGemm + nbS2) {
        int node = (bid - 2 * nbGemm) * 8 + warp;
        if (node < N) {
            float d = warp_dot256(x + (size_t)node * H, g_ws2, lane);
            if (!lane) g_s2[node] = d + g_consts[2];
        }
    } else {
        int pb = nbGemm + (bid - 2 * nbGemm - nbS2);
        pack_warp(adj, (size_t)pb * 8 + warp, lane);
    }
}

// ---------------- final edge kernel (decodes the lane-local bit layout) ----------------
__global__ void __launch_bounds__(256) edge_kernel(const int* __restrict__ tei, int E, int nwords,
                                                   const float* __restrict__ beta_p,
                                                   const int* __restrict__ boolen_p,
                                                   float* __restrict__ out) {
    int gw = (blockIdx.x * blockDim.x + threadIdx.x) >> 5;
    int lane = threadIdx.x & 31;
    if (gw >= E) return;

    int src = tei[gw];
    int dst = tei[E + gw];

    const uint32_t* bsrc = g_bits + (size_t)src * nwords;
    const uint32_t* bdst = g_bits + (size_t)dst * nwords;

    float s = 0.f;
    int rounds = nwords >> 5;          // 8 for N=8192
    for (int rb = 0; rb < rounds; rb += 8) {
        uint32_t aw[8], bw[8];
#pragma unroll
        for (int i = 0; i < 8; i++) {
            int w = lane + ((rb + i) << 5);
            aw[i] = bsrc[w];
            bw[i] = bdst[w];
        }
#pragma unroll
        for (int i = 0; i < 8; i++) {
            int w = lane + ((rb + i) << 5);
            uint32_t a = aw[i] & bw[i];
            if (a) {
                // decode: chunk = w>>6, L = (w&63)>>1, half = w&1
                int nb = ((w >> 6) << 11) + ((w & 1) << 10) + ((w >> 1) & 31) * 4;
                do {
                    int b = __ffs(a) - 1;
                    a &= a - 1;
                    s += g_s2[nb + ((b >> 2) << 7) + (b & 3)];
                } while (a);
            }
        }
    }
    float S = warp_red(s);

    if (!lane) {
        float beta = beta_p[0];
        float u = g_t0[gw] + g_t1[gw] + beta * (S + g_consts[0]) + g_consts[1];
        bool pos = boolen_p ? (boolen_p[0] != 0) : true;
        float v = pos ? u : -u;
        out[gw] = fmaxf(-v, 0.f) + log1pf(expf(-fabsf(v)));  // softplus(-v)
    }
}

// ---------------- launch ----------------
extern "C" void kernel_launch(void* const* d_in, const int* in_sizes, int n_in,
                              void* d_out, int out_size) {
    const float* x    = (const float*)d_in[0];
    const float* adj  = (const float*)d_in[1];
    const int*   tei  = (const int*)d_in[2];
    const float* Wlin = (const float*)d_in[3];
    const float* blin = (const float*)d_in[4];
    const float* Wcn  = (const float*)d_in[5];
    const float* bcn  = (const float*)d_in[6];
    const float* Wi   = (const float*)d_in[7];
    const float* bi   = (const float*)d_in[8];
    const float* Wj   = (const float*)d_in[9];
    const float* bj   = (const float*)d_in[10];
    const float* Wf   = (const float*)d_in[11];
    const float* bf   = (const float*)d_in[12];
    const float* ws   = (const float*)d_in[13];
    const float* bs   = (const float*)d_in[14];
    const float* beta = (const float*)d_in[15];
    const int* boolen = (n_in > 16) ? (const int*)d_in[16] : nullptr;
    float* out = (float*)d_out;

    const int N = in_sizes[0] / H;   // 8192 nodes
    const int E = in_sizes[2] / 2;   // 8192 edges
    const int nwords = N / 32;       // 256 words per adjacency row

    // 1) combo head: x split ∥ W split ∥ flag zero ∥ k0a
    combo_kernel<<<(NMAX * H) / 1024 + H + 32 + 2 * H, 256>>>(x, Wi, Wj, Wcn, Wf, ws);
    // 2) flags (after zeroing), then k0b (needs vcn)
    flagset_kernel<<<(2 * E + 255) / 256, 256>>>(tei, 2 * E);
    k0b_kernel<<<H + 3, 256>>>(Wlin, blin, bcn, bf, ws, bs);
    // 3) fused: shfl-free pack (DRAM) + tensor GEMM + s2 GEMV
    {
        int nbGemm = (E / 64) * 2;                        // 256
        int nbS2   = N / 8;                               // 1024
        int nbPack = (int)((long long)N * N / 2048 / 8);  // 4096
        int total = nbGemm + nbS2 + nbPack;               // 5376
        fused_kernel<<<total, 256>>>(x, adj, tei, bi, bj, N, E);
    }
    // 4) per-edge: CN bit-AND gather + combine + softplus
    edge_kernel<<<(E + 7) / 8, 256>>>(tei, E, nwords, beta, boolen, out);
}